// round 14
// baseline (speedup 1.0000x reference)
#include <cuda_runtime.h>
#include <math.h>

// ---------------- scratch (device globals: allocation-free) ----------------
#define NMAX 65536
__device__ float g_h[NMAX * 256];     // trunk output h
__device__ float g_out[NMAX * 256];   // gated expert output
__device__ int   g_top1[NMAX];
__device__ float g_gate[NMAX];
__device__ int   g_perm[NMAX];
__device__ int   g_counts[8];
__device__ int   g_cursor[8];

// ---------------- shared-memory layout (dynamic) ----------------
// A: 64 x 288 activations (padded for the 283-wide color input)
// B: 64 x 256 activations
// W: 16 x 256 weight staging tile
#define A_STRIDE 288
#define SM_B (64 * 288)
#define SM_W (64 * 288 + 64 * 256)
#define SMEM_FLOATS (64 * 288 + 64 * 256 + 16 * 256)

// ---------------- tiled GEMM: C[64, 32*NJ] = A(smem)[64,Kd] @ W(global)[Kd, ldw]
// 256 threads: tm = tid>>5 (0..7), tn = tid&31. Thread owns rows tm+8i,
// cols tn+32j (strided => conflict-free LDS + coalesced stores).
// Rows k >= Kreal are zero-filled in the staging tile (handles padded K).
template <int NJ>
__device__ __forceinline__ void gemm_tile(
    const float* __restrict__ Asm, int lda, int Kd, int Kreal,
    const float* __restrict__ Wglob, int ldw,
    float* __restrict__ Wsm,
    float (&acc)[8][NJ], int tm, int tn, int tid)
{
#pragma unroll
    for (int i = 0; i < 8; i++)
#pragma unroll
        for (int j = 0; j < NJ; j++) acc[i][j] = 0.f;

    const int NT = 32 * NJ;
    const int n4 = NT / 4;

    for (int k0 = 0; k0 < Kd; k0 += 16) {
        __syncthreads();  // protect Wsm (and order caller's smem writes)
        for (int it = tid; it < 16 * n4; it += 256) {
            int kk = it / n4;
            int c4 = it - kk * n4;
            int kr = k0 + kk;
            float4 v = make_float4(0.f, 0.f, 0.f, 0.f);
            if (kr < Kreal)
                v = *reinterpret_cast<const float4*>(Wglob + (size_t)kr * ldw + c4 * 4);
            reinterpret_cast<float4*>(Wsm + kk * NT)[c4] = v;
        }
        __syncthreads();
#pragma unroll
        for (int kk = 0; kk < 16; kk++) {
            float a[8];
#pragma unroll
            for (int i = 0; i < 8; i++) a[i] = Asm[(tm + 8 * i) * lda + (k0 + kk)];
            float w[NJ];
#pragma unroll
            for (int j = 0; j < NJ; j++) w[j] = Wsm[kk * NT + tn + 32 * j];
#pragma unroll
            for (int i = 0; i < 8; i++)
#pragma unroll
                for (int j = 0; j < NJ; j++) acc[i][j] = fmaf(a[i], w[j], acc[i][j]);
        }
    }
}

// ---------------- K1: posenc(xyz) -> trunk MLP -> gate/top1 ----------------
__global__ void __launch_bounds__(256, 1)
k_trunk(const float* __restrict__ xyz,
        const float* __restrict__ W1, const float* __restrict__ b1,
        const float* __restrict__ W2, const float* __restrict__ b2,
        const float* __restrict__ Wg, const float* __restrict__ bg,
        int N)
{
    extern __shared__ float sm[];
    float* A   = sm;
    float* B   = sm + SM_B;
    float* Wsm = sm + SM_W;
    const int tid = threadIdx.x, tm = tid >> 5, tn = tid & 31;
    const int base = blockIdx.x * 64;

    // positional encoding into A[64][64] (col 63 = zero pad; Kreal=63)
    for (int i = tid; i < 64 * 64; i += 256) {
        int m = i >> 6, c = i & 63;
        int gi = base + m; if (gi >= N) gi = N - 1;
        float val = 0.f;
        if (c < 3) {
            val = xyz[gi * 3 + c];
        } else if (c < 63) {
            int cc = c - 3, l = cc / 6, r = cc - 6 * l;
            float ax = xyz[gi * 3 + (r % 3)];
            float v = ax * (float)(1 << l);
            val = (r < 3) ? sinf(v) : cosf(v);
        }
        A[m * A_STRIDE + c] = val;
    }

    float acc[8][8];
    // h1 = relu(ex @ W1 + b1)
    gemm_tile<8>(A, A_STRIDE, 64, 63, W1, 256, Wsm, acc, tm, tn, tid);
#pragma unroll
    for (int i = 0; i < 8; i++)
#pragma unroll
        for (int j = 0; j < 8; j++) {
            int n = tn + 32 * j;
            B[(tm + 8 * i) * 256 + n] = fmaxf(acc[i][j] + b1[n], 0.f);
        }
    // h = h1 @ W2 + b2   (no activation)
    gemm_tile<8>(B, 256, 256, 256, W2, 256, Wsm, acc, tm, tn, tid);
#pragma unroll
    for (int i = 0; i < 8; i++)
#pragma unroll
        for (int j = 0; j < 8; j++) {
            int n = tn + 32 * j;
            A[(tm + 8 * i) * A_STRIDE + n] = acc[i][j] + b2[n];
        }
    __syncthreads();

    // gate logits into Wsm[64*8]
    for (int it = tid; it < 512; it += 256) {
        int m = it >> 3, e = it & 7;
        float s = bg[e];
        for (int k = 0; k < 256; k++) s = fmaf(A[m * A_STRIDE + k], Wg[k * 8 + e], s);
        Wsm[m * 8 + e] = s;
    }
    __syncthreads();

    if (tid < 64) {
        int gi = base + tid;
        if (gi < N) {
            float mx = Wsm[tid * 8]; int am = 0;
            for (int e = 1; e < 8; e++) { float v = Wsm[tid * 8 + e]; if (v > mx) { mx = v; am = e; } }
            float ssum = 0.f;
            for (int e = 0; e < 8; e++) ssum += expf(Wsm[tid * 8 + e] - mx);
            g_top1[gi] = am;
            g_gate[gi] = 1.f / ssum;       // softmax score at argmax
            atomicAdd(&g_counts[am], 1);
        }
    }

    // write h rows
    for (int i = tid; i < 64 * 64; i += 256) {
        int m = i >> 6, c4 = i & 63;
        int gi = base + m;
        if (gi < N)
            reinterpret_cast<float4*>(g_h + (size_t)gi * 256)[c4] =
                reinterpret_cast<const float4*>(A + m * A_STRIDE)[c4];
    }
}

// ---------------- routing helper kernels ----------------
__global__ void k_zero() {
    if (threadIdx.x < 8) g_counts[threadIdx.x] = 0;
}
__global__ void k_scan() {
    if (threadIdx.x == 0) {
        int off = 0;
        for (int e = 0; e < 8; e++) { g_cursor[e] = off; off += g_counts[e]; }
    }
}
__global__ void k_scatter(int N) {
    int i = blockIdx.x * 256 + threadIdx.x;
    if (i < N) {
        int e = g_top1[i];
        int pos = atomicAdd(&g_cursor[e], 1);
        g_perm[pos] = i;
    }
}

// ---------------- K4: routed expert MLP (4 layers, skip at layer 1) ----------------
__global__ void __launch_bounds__(256, 1)
k_expert(const float* __restrict__ We, const float* __restrict__ be, int N)
{
    extern __shared__ float sm[];
    float* A   = sm;
    float* B   = sm + SM_B;
    float* Wsm = sm + SM_W;
    __shared__ int   s_idx[64];
    __shared__ int   s_eo[64];
    __shared__ float s_gt[64];
    __shared__ int   s_mask;

    const int tid = threadIdx.x, tm = tid >> 5, tn = tid & 31;
    const int base = blockIdx.x * 64;

    if (tid < 64) {
        int gi = base + tid;
        int p = (gi < N) ? g_perm[gi] : -1;
        s_idx[tid] = p;
        s_eo[tid]  = (p >= 0) ? g_top1[p] : -1;
        s_gt[tid]  = (p >= 0) ? g_gate[p] : 0.f;
    }
    __syncthreads();
    if (tid == 0) {
        int mk = 0;
        for (int m = 0; m < 64; m++) if (s_eo[m] >= 0) mk |= 1 << s_eo[m];
        s_mask = mk;
    }
    __syncthreads();
    const int mask = s_mask;

    float acc[8][8];
    for (int e = 0; e < 8; e++) {
        if (!((mask >> e) & 1)) continue;

        // (re)load h rows into A (x for the skip connection)
        for (int i = tid; i < 64 * 64; i += 256) {
            int m = i >> 6, c4 = i & 63;
            int p = s_idx[m];
            float4 v = make_float4(0.f, 0.f, 0.f, 0.f);
            if (p >= 0) v = reinterpret_cast<const float4*>(g_h + (size_t)p * 256)[c4];
            reinterpret_cast<float4*>(A + m * A_STRIDE)[c4] = v;
        }

        const float* W  = We + (size_t)e * 4 * 256 * 256;
        const float* bb = be + (size_t)e * 4 * 256;

        // layer 0: B = relu(A @ W0 + b0)
        gemm_tile<8>(A, A_STRIDE, 256, 256, W, 256, Wsm, acc, tm, tn, tid);
#pragma unroll
        for (int i = 0; i < 8; i++)
#pragma unroll
            for (int j = 0; j < 8; j++) {
                int n = tn + 32 * j;
                B[(tm + 8 * i) * 256 + n] = fmaxf(acc[i][j] + bb[n], 0.f);
            }
        // layer 1 (skip): A = relu(B @ W1 + b1 + A)
        gemm_tile<8>(B, 256, 256, 256, W + 65536, 256, Wsm, acc, tm, tn, tid);
#pragma unroll
        for (int i = 0; i < 8; i++)
#pragma unroll
            for (int j = 0; j < 8; j++) {
                int n = tn + 32 * j, m = tm + 8 * i;
                float t = acc[i][j] + bb[256 + n] + A[m * A_STRIDE + n];
                A[m * A_STRIDE + n] = fmaxf(t, 0.f);
            }
        // layer 2: B = relu(A @ W2 + b2)
        gemm_tile<8>(A, A_STRIDE, 256, 256, W + 2 * 65536, 256, Wsm, acc, tm, tn, tid);
#pragma unroll
        for (int i = 0; i < 8; i++)
#pragma unroll
            for (int j = 0; j < 8; j++) {
                int n = tn + 32 * j;
                B[(tm + 8 * i) * 256 + n] = fmaxf(acc[i][j] + bb[512 + n], 0.f);
            }
        // layer 3: out = gate * (B @ W3 + b3), masked store
        gemm_tile<8>(B, 256, 256, 256, W + 3 * 65536, 256, Wsm, acc, tm, tn, tid);
#pragma unroll
        for (int i = 0; i < 8; i++) {
            int m = tm + 8 * i;
            if (s_eo[m] == e) {
                int p = s_idx[m];
                float g = s_gt[m];
#pragma unroll
                for (int j = 0; j < 8; j++) {
                    int n = tn + 32 * j;
                    g_out[(size_t)p * 256 + n] = g * (acc[i][j] + bb[768 + n]);
                }
            }
        }
        __syncthreads();
    }
}

// ---------------- K5: sigma head + color head ----------------
__global__ void __launch_bounds__(256, 1)
k_heads(const float* __restrict__ dirs,
        const float* __restrict__ Ws1, const float* __restrict__ bs1,
        const float* __restrict__ Ws2, const float* __restrict__ bs2,
        const float* __restrict__ Wc1, const float* __restrict__ bc1,
        const float* __restrict__ Wc2, const float* __restrict__ bc2,
        float* __restrict__ out, int N)
{
    extern __shared__ float sm[];
    float* A   = sm;
    float* B   = sm + SM_B;          // c1: 64 x 128
    float* Bs  = B + 64 * 128;       // s1: 64 x 128
    float* Wsm = sm + SM_W;
    const int tid = threadIdx.x, tm = tid >> 5, tn = tid & 31;
    const int base = blockIdx.x * 64;

    // cin = [out(256), posenc(dirs)(27), pad(5 zeros)]
    for (int i = tid; i < 64 * 64; i += 256) {
        int m = i >> 6, c4 = i & 63;
        int gi = base + m; if (gi >= N) gi = N - 1;
        reinterpret_cast<float4*>(A + m * A_STRIDE)[c4] =
            reinterpret_cast<const float4*>(g_out + (size_t)gi * 256)[c4];
    }
    for (int i = tid; i < 64 * 32; i += 256) {
        int m = i >> 5, c = i & 31;
        int gi = base + m; if (gi >= N) gi = N - 1;
        float val = 0.f;
        if (c < 27) {
            if (c < 3) {
                val = dirs[gi * 3 + c];
            } else {
                int cc = c - 3, l = cc / 6, r = cc - 6 * l;
                float ax = dirs[gi * 3 + (r % 3)];
                float v = ax * (float)(1 << l);
                val = (r < 3) ? sinf(v) : cosf(v);
            }
        }
        A[m * A_STRIDE + 256 + c] = val;
    }

    float acc[8][4];
    // c1 = relu(cin @ Wc1 + bc1)   (Kd padded 288, real 283)
    gemm_tile<4>(A, A_STRIDE, 288, 283, Wc1, 128, Wsm, acc, tm, tn, tid);
#pragma unroll
    for (int i = 0; i < 8; i++)
#pragma unroll
        for (int j = 0; j < 4; j++) {
            int n = tn + 32 * j;
            B[(tm + 8 * i) * 128 + n] = fmaxf(acc[i][j] + bc1[n], 0.f);
        }
    __syncthreads();

    // rgb = sigmoid(c1 @ Wc2 + bc2)
    for (int it = tid; it < 192; it += 256) {
        int m = it / 3, ch = it - 3 * m;
        float s = bc2[ch];
        for (int k = 0; k < 128; k++) s = fmaf(B[m * 128 + k], Wc2[k * 3 + ch], s);
        int gi = base + m;
        if (gi < N) out[gi * 4 + ch] = 1.f / (1.f + expf(-s));
    }

    // s1 = relu(out @ Ws1 + bs1)   (only first 256 cols of A)
    gemm_tile<4>(A, A_STRIDE, 256, 256, Ws1, 128, Wsm, acc, tm, tn, tid);
#pragma unroll
    for (int i = 0; i < 8; i++)
#pragma unroll
        for (int j = 0; j < 4; j++) {
            int n = tn + 32 * j;
            Bs[(tm + 8 * i) * 128 + n] = fmaxf(acc[i][j] + bs1[n], 0.f);
        }
    __syncthreads();

    // sigma = softplus(s1 @ Ws2 + bs2)
    if (tid < 64) {
        int m = tid;
        float s = bs2[0];
        for (int k = 0; k < 128; k++) s = fmaf(Bs[m * 128 + k], Ws2[k], s);
        int gi = base + m;
        if (gi < N) {
            float sp = fmaxf(s, 0.f) + log1pf(expf(-fabsf(s)));
            out[gi * 4 + 3] = sp;
        }
    }
}

// ---------------- launch ----------------
extern "C" void kernel_launch(void* const* d_in, const int* in_sizes, int n_in,
                              void* d_out, int out_size)
{
    const float* xyz  = (const float*)d_in[0];
    const float* dirs = (const float*)d_in[1];
    const float* W1   = (const float*)d_in[2];
    const float* b1   = (const float*)d_in[3];
    const float* W2   = (const float*)d_in[4];
    const float* b2   = (const float*)d_in[5];
    const float* Wg   = (const float*)d_in[6];
    const float* bg   = (const float*)d_in[7];
    const float* We   = (const float*)d_in[8];
    const float* be   = (const float*)d_in[9];
    const float* Ws1  = (const float*)d_in[10];
    const float* bs1  = (const float*)d_in[11];
    const float* Ws2  = (const float*)d_in[12];
    const float* bs2  = (const float*)d_in[13];
    const float* Wc1  = (const float*)d_in[14];
    const float* bc1  = (const float*)d_in[15];
    const float* Wc2  = (const float*)d_in[16];
    const float* bc2  = (const float*)d_in[17];

    int N = in_sizes[0] / 3;
    if (N > NMAX) N = NMAX;

    const size_t smem = SMEM_FLOATS * sizeof(float);  // ~152 KB
    cudaFuncSetAttribute(k_trunk,  cudaFuncAttributeMaxDynamicSharedMemorySize, (int)smem);
    cudaFuncSetAttribute(k_expert, cudaFuncAttributeMaxDynamicSharedMemorySize, (int)smem);
    cudaFuncSetAttribute(k_heads,  cudaFuncAttributeMaxDynamicSharedMemorySize, (int)smem);

    int nb = (N + 63) / 64;

    k_zero<<<1, 32>>>();
    k_trunk<<<nb, 256, smem>>>(xyz, W1, b1, W2, b2, Wg, bg, N);
    k_scan<<<1, 32>>>();
    k_scatter<<<(N + 255) / 256, 256>>>(N);
    k_expert<<<nb, 256, smem>>>(We, be, N);
    k_heads<<<nb, 256, smem>>>(dirs, Ws1, bs1, Ws2, bs2, Wc1, bc1, Wc2, bc2,
                               (float*)d_out, N);
}

// round 15
// speedup vs baseline: 1.0722x; 1.0722x over previous
#include <cuda_runtime.h>
#include <math.h>

// ---------------- scratch (device globals: allocation-free) ----------------
#define NMAX 65536
__device__ float g_h[NMAX * 256];     // trunk output h
__device__ float g_out[NMAX * 256];   // gated expert output
__device__ int   g_top1[NMAX];
__device__ float g_gate[NMAX];
__device__ int   g_perm[NMAX];
__device__ int   g_counts[8];
__device__ int   g_cursor[8];

// ---------------- shared-memory layout (dynamic) ----------------
#define A_STRIDE 288
#define SM_B (64 * 288)
#define SM_W (64 * 288 + 64 * 256)
#define SMEM_FLOATS (64 * 288 + 64 * 256 + 16 * 256)

// ---------------- packed f32x2 helpers (FFMA2: 2x fp32 rate, exact) --------
typedef unsigned long long u64;

__device__ __forceinline__ u64 pack2(float lo, float hi) {
    u64 r;
    asm("mov.b64 %0, {%1, %2};" : "=l"(r) : "f"(lo), "f"(hi));
    return r;
}
__device__ __forceinline__ void unpack2(u64 v, float& lo, float& hi) {
    asm("mov.b64 {%0, %1}, %2;" : "=f"(lo), "=f"(hi) : "l"(v));
}
__device__ __forceinline__ u64 fma2(u64 a, u64 b, u64 c) {
    u64 d;
    asm("fma.rn.f32x2 %0, %1, %2, %3;" : "=l"(d) : "l"(a), "l"(b), "l"(c));
    return d;
}

// ---------------- tiled GEMM: C[64, 64*NJP] = A(smem)[64,Kd] @ W(glob)[Kd,ldw]
// 256 threads: tm = tid>>5 (rows tm+8i), tn = tid&31.
// Thread owns COLUMN PAIRS: cols (2*tn + 64*j, +1) for j<NJP.
//  - W fragment = one LDS.64 per pair (conflict-free: 32 lanes x 8B consecutive)
//  - A value broadcast-packed {a,a} once per row per k
//  - inner product = fma.rn.f32x2 (2 exact fp32 FMAs / issue)
// Rows k >= Kreal are zero-filled in the staging tile (handles padded K).
template <int NJP>
__device__ __forceinline__ void gemm_tile2(
    const float* __restrict__ Asm, int lda, int Kd, int Kreal,
    const float* __restrict__ Wglob, int ldw,
    float* __restrict__ Wsm,
    u64 (&acc)[8][NJP], int tm, int tn, int tid)
{
#pragma unroll
    for (int i = 0; i < 8; i++)
#pragma unroll
        for (int j = 0; j < NJP; j++) acc[i][j] = 0ULL;

    const int NT = 64 * NJP;
    const int n4 = NT / 4;

    for (int k0 = 0; k0 < Kd; k0 += 16) {
        __syncthreads();  // protect Wsm (and order caller's smem writes)
        for (int it = tid; it < 16 * n4; it += 256) {
            int kk = it / n4;
            int c4 = it - kk * n4;
            int kr = k0 + kk;
            float4 v = make_float4(0.f, 0.f, 0.f, 0.f);
            if (kr < Kreal)
                v = *reinterpret_cast<const float4*>(Wglob + (size_t)kr * ldw + c4 * 4);
            reinterpret_cast<float4*>(Wsm + kk * NT)[c4] = v;
        }
        __syncthreads();
#pragma unroll
        for (int kk = 0; kk < 16; kk++) {
            u64 a2[8];
#pragma unroll
            for (int i = 0; i < 8; i++) {
                float a = Asm[(tm + 8 * i) * lda + (k0 + kk)];
                a2[i] = pack2(a, a);
            }
            u64 w2[NJP];
#pragma unroll
            for (int j = 0; j < NJP; j++)
                w2[j] = *reinterpret_cast<const u64*>(Wsm + kk * NT + 2 * tn + 64 * j);
#pragma unroll
            for (int i = 0; i < 8; i++)
#pragma unroll
                for (int j = 0; j < NJP; j++) acc[i][j] = fma2(a2[i], w2[j], acc[i][j]);
        }
    }
}

// ---------------- K1: posenc(xyz) -> trunk MLP -> gate/top1 ----------------
__global__ void __launch_bounds__(256, 1)
k_trunk(const float* __restrict__ xyz,
        const float* __restrict__ W1, const float* __restrict__ b1,
        const float* __restrict__ W2, const float* __restrict__ b2,
        const float* __restrict__ Wg, const float* __restrict__ bg,
        int N)
{
    extern __shared__ float sm[];
    float* A   = sm;
    float* B   = sm + SM_B;
    float* Wsm = sm + SM_W;
    const int tid = threadIdx.x, tm = tid >> 5, tn = tid & 31;
    const int base = blockIdx.x * 64;

    // positional encoding into A[64][64] (col 63 = zero pad; Kreal=63)
    for (int i = tid; i < 64 * 64; i += 256) {
        int m = i >> 6, c = i & 63;
        int gi = base + m; if (gi >= N) gi = N - 1;
        float val = 0.f;
        if (c < 3) {
            val = xyz[gi * 3 + c];
        } else if (c < 63) {
            int cc = c - 3, l = cc / 6, r = cc - 6 * l;
            float ax = xyz[gi * 3 + (r % 3)];
            float v = ax * (float)(1 << l);
            val = (r < 3) ? sinf(v) : cosf(v);
        }
        A[m * A_STRIDE + c] = val;
    }

    u64 acc[8][4];
    // h1 = relu(ex @ W1 + b1)
    gemm_tile2<4>(A, A_STRIDE, 64, 63, W1, 256, Wsm, acc, tm, tn, tid);
#pragma unroll
    for (int i = 0; i < 8; i++)
#pragma unroll
        for (int j = 0; j < 4; j++) {
            int n = 2 * tn + 64 * j, m = tm + 8 * i;
            float lo, hi; unpack2(acc[i][j], lo, hi);
            B[m * 256 + n]     = fmaxf(lo + b1[n], 0.f);
            B[m * 256 + n + 1] = fmaxf(hi + b1[n + 1], 0.f);
        }
    // h = h1 @ W2 + b2   (no activation)
    gemm_tile2<4>(B, 256, 256, 256, W2, 256, Wsm, acc, tm, tn, tid);
#pragma unroll
    for (int i = 0; i < 8; i++)
#pragma unroll
        for (int j = 0; j < 4; j++) {
            int n = 2 * tn + 64 * j, m = tm + 8 * i;
            float lo, hi; unpack2(acc[i][j], lo, hi);
            A[m * A_STRIDE + n]     = lo + b2[n];
            A[m * A_STRIDE + n + 1] = hi + b2[n + 1];
        }
    __syncthreads();

    // gate logits into Wsm[64*8]
    for (int it = tid; it < 512; it += 256) {
        int m = it >> 3, e = it & 7;
        float s = bg[e];
        for (int k = 0; k < 256; k++) s = fmaf(A[m * A_STRIDE + k], Wg[k * 8 + e], s);
        Wsm[m * 8 + e] = s;
    }
    __syncthreads();

    if (tid < 64) {
        int gi = base + tid;
        if (gi < N) {
            float mx = Wsm[tid * 8]; int am = 0;
            for (int e = 1; e < 8; e++) { float v = Wsm[tid * 8 + e]; if (v > mx) { mx = v; am = e; } }
            float ssum = 0.f;
            for (int e = 0; e < 8; e++) ssum += expf(Wsm[tid * 8 + e] - mx);
            g_top1[gi] = am;
            g_gate[gi] = 1.f / ssum;       // softmax score at argmax
            atomicAdd(&g_counts[am], 1);
        }
    }

    // write h rows
    for (int i = tid; i < 64 * 64; i += 256) {
        int m = i >> 6, c4 = i & 63;
        int gi = base + m;
        if (gi < N)
            reinterpret_cast<float4*>(g_h + (size_t)gi * 256)[c4] =
                reinterpret_cast<const float4*>(A + m * A_STRIDE)[c4];
    }
}

// ---------------- routing helper kernels ----------------
__global__ void k_zero() {
    if (threadIdx.x < 8) g_counts[threadIdx.x] = 0;
}
__global__ void k_scan() {
    if (threadIdx.x == 0) {
        int off = 0;
        for (int e = 0; e < 8; e++) { g_cursor[e] = off; off += g_counts[e]; }
    }
}
__global__ void k_scatter(int N) {
    int i = blockIdx.x * 256 + threadIdx.x;
    if (i < N) {
        int e = g_top1[i];
        int pos = atomicAdd(&g_cursor[e], 1);
        g_perm[pos] = i;
    }
}

// ---------------- K4: routed expert MLP (4 layers, skip at layer 1) --------
__global__ void __launch_bounds__(256, 1)
k_expert(const float* __restrict__ We, const float* __restrict__ be, int N)
{
    extern __shared__ float sm[];
    float* A   = sm;
    float* B   = sm + SM_B;
    float* Wsm = sm + SM_W;
    __shared__ int   s_idx[64];
    __shared__ int   s_eo[64];
    __shared__ float s_gt[64];
    __shared__ int   s_mask;

    const int tid = threadIdx.x, tm = tid >> 5, tn = tid & 31;
    const int base = blockIdx.x * 64;

    if (tid < 64) {
        int gi = base + tid;
        int p = (gi < N) ? g_perm[gi] : -1;
        s_idx[tid] = p;
        s_eo[tid]  = (p >= 0) ? g_top1[p] : -1;
        s_gt[tid]  = (p >= 0) ? g_gate[p] : 0.f;
    }
    __syncthreads();
    if (tid == 0) {
        int mk = 0;
        for (int m = 0; m < 64; m++) if (s_eo[m] >= 0) mk |= 1 << s_eo[m];
        s_mask = mk;
    }
    __syncthreads();
    const int mask = s_mask;

    u64 acc[8][4];
    for (int e = 0; e < 8; e++) {
        if (!((mask >> e) & 1)) continue;

        // (re)load h rows into A (x for the skip connection)
        for (int i = tid; i < 64 * 64; i += 256) {
            int m = i >> 6, c4 = i & 63;
            int p = s_idx[m];
            float4 v = make_float4(0.f, 0.f, 0.f, 0.f);
            if (p >= 0) v = reinterpret_cast<const float4*>(g_h + (size_t)p * 256)[c4];
            reinterpret_cast<float4*>(A + m * A_STRIDE)[c4] = v;
        }

        const float* W  = We + (size_t)e * 4 * 256 * 256;
        const float* bb = be + (size_t)e * 4 * 256;

        // layer 0: B = relu(A @ W0 + b0)
        gemm_tile2<4>(A, A_STRIDE, 256, 256, W, 256, Wsm, acc, tm, tn, tid);
#pragma unroll
        for (int i = 0; i < 8; i++)
#pragma unroll
            for (int j = 0; j < 4; j++) {
                int n = 2 * tn + 64 * j, m = tm + 8 * i;
                float lo, hi; unpack2(acc[i][j], lo, hi);
                B[m * 256 + n]     = fmaxf(lo + bb[n], 0.f);
                B[m * 256 + n + 1] = fmaxf(hi + bb[n + 1], 0.f);
            }
        // layer 1 (skip): A = relu(B @ W1 + b1 + A)
        gemm_tile2<4>(B, 256, 256, 256, W + 65536, 256, Wsm, acc, tm, tn, tid);
#pragma unroll
        for (int i = 0; i < 8; i++)
#pragma unroll
            for (int j = 0; j < 4; j++) {
                int n = 2 * tn + 64 * j, m = tm + 8 * i;
                float lo, hi; unpack2(acc[i][j], lo, hi);
                float t0 = lo + bb[256 + n]     + A[m * A_STRIDE + n];
                float t1 = hi + bb[256 + n + 1] + A[m * A_STRIDE + n + 1];
                A[m * A_STRIDE + n]     = fmaxf(t0, 0.f);
                A[m * A_STRIDE + n + 1] = fmaxf(t1, 0.f);
            }
        // layer 2: B = relu(A @ W2 + b2)
        gemm_tile2<4>(A, A_STRIDE, 256, 256, W + 2 * 65536, 256, Wsm, acc, tm, tn, tid);
#pragma unroll
        for (int i = 0; i < 8; i++)
#pragma unroll
            for (int j = 0; j < 4; j++) {
                int n = 2 * tn + 64 * j, m = tm + 8 * i;
                float lo, hi; unpack2(acc[i][j], lo, hi);
                B[m * 256 + n]     = fmaxf(lo + bb[512 + n], 0.f);
                B[m * 256 + n + 1] = fmaxf(hi + bb[512 + n + 1], 0.f);
            }
        // layer 3: out = gate * (B @ W3 + b3), masked store
        gemm_tile2<4>(B, 256, 256, 256, W + 3 * 65536, 256, Wsm, acc, tm, tn, tid);
#pragma unroll
        for (int i = 0; i < 8; i++) {
            int m = tm + 8 * i;
            if (s_eo[m] == e) {
                int p = s_idx[m];
                float g = s_gt[m];
#pragma unroll
                for (int j = 0; j < 4; j++) {
                    int n = 2 * tn + 64 * j;
                    float lo, hi; unpack2(acc[i][j], lo, hi);
                    g_out[(size_t)p * 256 + n]     = g * (lo + bb[768 + n]);
                    g_out[(size_t)p * 256 + n + 1] = g * (hi + bb[768 + n + 1]);
                }
            }
        }
        __syncthreads();
    }
}

// ---------------- K5: sigma head + color head ----------------
__global__ void __launch_bounds__(256, 1)
k_heads(const float* __restrict__ dirs,
        const float* __restrict__ Ws1, const float* __restrict__ bs1,
        const float* __restrict__ Ws2, const float* __restrict__ bs2,
        const float* __restrict__ Wc1, const float* __restrict__ bc1,
        const float* __restrict__ Wc2, const float* __restrict__ bc2,
        float* __restrict__ out, int N)
{
    extern __shared__ float sm[];
    float* A   = sm;
    float* B   = sm + SM_B;          // c1: 64 x 128
    float* Bs  = B + 64 * 128;       // s1: 64 x 128
    float* Wsm = sm + SM_W;
    const int tid = threadIdx.x, tm = tid >> 5, tn = tid & 31;
    const int base = blockIdx.x * 64;

    // cin = [out(256), posenc(dirs)(27), pad(5 zeros)]
    for (int i = tid; i < 64 * 64; i += 256) {
        int m = i >> 6, c4 = i & 63;
        int gi = base + m; if (gi >= N) gi = N - 1;
        reinterpret_cast<float4*>(A + m * A_STRIDE)[c4] =
            reinterpret_cast<const float4*>(g_out + (size_t)gi * 256)[c4];
    }
    for (int i = tid; i < 64 * 32; i += 256) {
        int m = i >> 5, c = i & 31;
        int gi = base + m; if (gi >= N) gi = N - 1;
        float val = 0.f;
        if (c < 27) {
            if (c < 3) {
                val = dirs[gi * 3 + c];
            } else {
                int cc = c - 3, l = cc / 6, r = cc - 6 * l;
                float ax = dirs[gi * 3 + (r % 3)];
                float v = ax * (float)(1 << l);
                val = (r < 3) ? sinf(v) : cosf(v);
            }
        }
        A[m * A_STRIDE + 256 + c] = val;
    }

    u64 acc[8][2];
    // c1 = relu(cin @ Wc1 + bc1)   (Kd padded 288, real 283)
    gemm_tile2<2>(A, A_STRIDE, 288, 283, Wc1, 128, Wsm, acc, tm, tn, tid);
#pragma unroll
    for (int i = 0; i < 8; i++)
#pragma unroll
        for (int j = 0; j < 2; j++) {
            int n = 2 * tn + 64 * j, m = tm + 8 * i;
            float lo, hi; unpack2(acc[i][j], lo, hi);
            B[m * 128 + n]     = fmaxf(lo + bc1[n], 0.f);
            B[m * 128 + n + 1] = fmaxf(hi + bc1[n + 1], 0.f);
        }
    __syncthreads();

    // rgb = sigmoid(c1 @ Wc2 + bc2)
    for (int it = tid; it < 192; it += 256) {
        int m = it / 3, ch = it - 3 * m;
        float s = bc2[ch];
        for (int k = 0; k < 128; k++) s = fmaf(B[m * 128 + k], Wc2[k * 3 + ch], s);
        int gi = base + m;
        if (gi < N) out[gi * 4 + ch] = 1.f / (1.f + expf(-s));
    }

    // s1 = relu(out @ Ws1 + bs1)   (only first 256 cols of A)
    gemm_tile2<2>(A, A_STRIDE, 256, 256, Ws1, 128, Wsm, acc, tm, tn, tid);
#pragma unroll
    for (int i = 0; i < 8; i++)
#pragma unroll
        for (int j = 0; j < 2; j++) {
            int n = 2 * tn + 64 * j, m = tm + 8 * i;
            float lo, hi; unpack2(acc[i][j], lo, hi);
            Bs[m * 128 + n]     = fmaxf(lo + bs1[n], 0.f);
            Bs[m * 128 + n + 1] = fmaxf(hi + bs1[n + 1], 0.f);
        }
    __syncthreads();

    // sigma = softplus(s1 @ Ws2 + bs2)
    if (tid < 64) {
        int m = tid;
        float s = bs2[0];
        for (int k = 0; k < 128; k++) s = fmaf(Bs[m * 128 + k], Ws2[k], s);
        int gi = base + m;
        if (gi < N) {
            float sp = fmaxf(s, 0.f) + log1pf(expf(-fabsf(s)));
            out[gi * 4 + 3] = sp;
        }
    }
}

// ---------------- launch ----------------
extern "C" void kernel_launch(void* const* d_in, const int* in_sizes, int n_in,
                              void* d_out, int out_size)
{
    const float* xyz  = (const float*)d_in[0];
    const float* dirs = (const float*)d_in[1];
    const float* W1   = (const float*)d_in[2];
    const float* b1   = (const float*)d_in[3];
    const float* W2   = (const float*)d_in[4];
    const float* b2   = (const float*)d_in[5];
    const float* Wg   = (const float*)d_in[6];
    const float* bg   = (const float*)d_in[7];
    const float* We   = (const float*)d_in[8];
    const float* be   = (const float*)d_in[9];
    const float* Ws1  = (const float*)d_in[10];
    const float* bs1  = (const float*)d_in[11];
    const float* Ws2  = (const float*)d_in[12];
    const float* bs2  = (const float*)d_in[13];
    const float* Wc1  = (const float*)d_in[14];
    const float* bc1  = (const float*)d_in[15];
    const float* Wc2  = (const float*)d_in[16];
    const float* bc2  = (const float*)d_in[17];

    int N = in_sizes[0] / 3;
    if (N > NMAX) N = NMAX;

    const size_t smem = SMEM_FLOATS * sizeof(float);  // ~152 KB
    cudaFuncSetAttribute(k_trunk,  cudaFuncAttributeMaxDynamicSharedMemorySize, (int)smem);
    cudaFuncSetAttribute(k_expert, cudaFuncAttributeMaxDynamicSharedMemorySize, (int)smem);
    cudaFuncSetAttribute(k_heads,  cudaFuncAttributeMaxDynamicSharedMemorySize, (int)smem);

    int nb = (N + 63) / 64;

    k_zero<<<1, 32>>>();
    k_trunk<<<nb, 256, smem>>>(xyz, W1, b1, W2, b2, Wg, bg, N);
    k_scan<<<1, 32>>>();
    k_scatter<<<(N + 255) / 256, 256>>>(N);
    k_expert<<<nb, 256, smem>>>(We, be, N);
    k_heads<<<nb, 256, smem>>>(dirs, Ws1, bs1, Ws2, bs2, Wc1, bc1, Wc2, bc2,
                               (float*)d_out, N);
}

// round 16
// speedup vs baseline: 1.5729x; 1.4669x over previous
#include <cuda_runtime.h>
#include <math.h>

// ---------------- scratch (device globals: allocation-free) ----------------
#define NMAX 65536
__device__ float g_h[NMAX * 256];     // trunk output h
__device__ float g_out[NMAX * 256];   // gated expert output
__device__ int   g_top1[NMAX];
__device__ float g_gate[NMAX];
__device__ int   g_perm[NMAX];
__device__ int   g_counts[8];
__device__ int   g_cursor[8];

// ---------------- shared-memory layout (dynamic) ----------------
// A: 64 x 288, B: 64 x 256, W: DOUBLE-BUFFERED 2 x 16 x 256 staging tiles
#define A_STRIDE 288
#define SM_B (64 * 288)
#define SM_W (64 * 288 + 64 * 256)
#define SMEM_FLOATS (64 * 288 + 64 * 256 + 2 * 16 * 256)

// ---------------- packed f32x2 helpers (FFMA2: 2x fp32 rate, exact) --------
typedef unsigned long long u64;

__device__ __forceinline__ u64 pack2(float lo, float hi) {
    u64 r;
    asm("mov.b64 %0, {%1, %2};" : "=l"(r) : "f"(lo), "f"(hi));
    return r;
}
__device__ __forceinline__ void unpack2(u64 v, float& lo, float& hi) {
    asm("mov.b64 {%0, %1}, %2;" : "=f"(lo), "=f"(hi) : "l"(v));
}
__device__ __forceinline__ u64 fma2(u64 a, u64 b, u64 c) {
    u64 d;
    asm("fma.rn.f32x2 %0, %1, %2, %3;" : "=l"(d) : "l"(a), "l"(b), "l"(c));
    return d;
}

// ---------------- async weight staging (cp.async, zfill for padded rows) ---
template <int NJP>
__device__ __forceinline__ void stage(
    const float* __restrict__ Wglob, int ldw, int k0, int Kreal,
    float* __restrict__ buf, int tid)
{
    const int NT = 64 * NJP;
    const int n4 = NT / 4;
#pragma unroll
    for (int t = 0; t < (16 * n4) / 256; t++) {
        int it = tid + t * 256;
        int kk = it / n4;
        int c4 = it - kk * n4;
        int kr = k0 + kk;
        int krc = (kr < Kreal) ? kr : (Kreal - 1);
        const float* src = Wglob + (size_t)krc * ldw + c4 * 4;
        unsigned dst = (unsigned)__cvta_generic_to_shared(buf + kk * NT + c4 * 4);
        int sz = (kr < Kreal) ? 16 : 0;    // zfill padded K rows
        asm volatile("cp.async.cg.shared.global [%0], [%1], 16, %2;\n"
                     :: "r"(dst), "l"(src), "r"(sz));
    }
    asm volatile("cp.async.commit_group;\n" ::: "memory");
}

// ---------------- tiled GEMM: C[64, 64*NJP] = A(smem)[64,Kd] @ W(glob)[Kd,ldw]
// 256 threads: tm = tid>>5 (rows tm+8i), tn = tid&31; thread owns column
// pairs (2*tn + 64*j). Weight tiles double-buffered via cp.async so the
// global->smem latency hides under the FFMA2 compute of the previous chunk.
// One __syncthreads per chunk: makes staged chunk c visible AND guards
// reuse of buffer (c+1)&1 (last read during compute of chunk c-1).
// Note: all Kd used here give an even chunk count, so the NEXT gemm's
// prologue (buf0) never collides with lagging reads of the final chunk (buf1).
template <int NJP>
__device__ __forceinline__ void gemm_tile2(
    const float* __restrict__ Asm, int lda, int Kd, int Kreal,
    const float* __restrict__ Wglob, int ldw,
    float* __restrict__ Wsm,
    u64 (&acc)[8][NJP], int tm, int tn, int tid)
{
#pragma unroll
    for (int i = 0; i < 8; i++)
#pragma unroll
        for (int j = 0; j < NJP; j++) acc[i][j] = 0ULL;

    const int NT = 64 * NJP;
    const int nch = Kd / 16;

    stage<NJP>(Wglob, ldw, 0, Kreal, Wsm, tid);

    for (int c = 0; c < nch; c++) {
        asm volatile("cp.async.wait_group 0;\n" ::: "memory");
        __syncthreads();
        if (c + 1 < nch)
            stage<NJP>(Wglob, ldw, (c + 1) * 16, Kreal,
                       Wsm + ((c + 1) & 1) * 16 * NT, tid);
        const float* __restrict__ Wb = Wsm + (c & 1) * 16 * NT;
        const int k0 = c * 16;
#pragma unroll
        for (int kk = 0; kk < 16; kk++) {
            u64 a2[8];
#pragma unroll
            for (int i = 0; i < 8; i++) {
                float a = Asm[(tm + 8 * i) * lda + (k0 + kk)];
                a2[i] = pack2(a, a);
            }
            u64 w2[NJP];
#pragma unroll
            for (int j = 0; j < NJP; j++)
                w2[j] = *reinterpret_cast<const u64*>(Wb + kk * NT + 2 * tn + 64 * j);
#pragma unroll
            for (int i = 0; i < 8; i++)
#pragma unroll
                for (int j = 0; j < NJP; j++) acc[i][j] = fma2(a2[i], w2[j], acc[i][j]);
        }
    }
}

// ---------------- K1: posenc(xyz) -> trunk MLP -> gate/top1 ----------------
__global__ void __launch_bounds__(256, 1)
k_trunk(const float* __restrict__ xyz,
        const float* __restrict__ W1, const float* __restrict__ b1,
        const float* __restrict__ W2, const float* __restrict__ b2,
        const float* __restrict__ Wg, const float* __restrict__ bg,
        int N)
{
    extern __shared__ float sm[];
    float* A   = sm;
    float* B   = sm + SM_B;
    float* Wsm = sm + SM_W;
    const int tid = threadIdx.x, tm = tid >> 5, tn = tid & 31;
    const int base = blockIdx.x * 64;

    // positional encoding into A[64][64] (col 63 = zero pad; Kreal=63)
    for (int i = tid; i < 64 * 64; i += 256) {
        int m = i >> 6, c = i & 63;
        int gi = base + m; if (gi >= N) gi = N - 1;
        float val = 0.f;
        if (c < 3) {
            val = xyz[gi * 3 + c];
        } else if (c < 63) {
            int cc = c - 3, l = cc / 6, r = cc - 6 * l;
            float ax = xyz[gi * 3 + (r % 3)];
            float v = ax * (float)(1 << l);
            val = (r < 3) ? sinf(v) : cosf(v);
        }
        A[m * A_STRIDE + c] = val;
    }

    u64 acc[8][4];
    // h1 = relu(ex @ W1 + b1)
    gemm_tile2<4>(A, A_STRIDE, 64, 63, W1, 256, Wsm, acc, tm, tn, tid);
#pragma unroll
    for (int i = 0; i < 8; i++)
#pragma unroll
        for (int j = 0; j < 4; j++) {
            int n = 2 * tn + 64 * j, m = tm + 8 * i;
            float lo, hi; unpack2(acc[i][j], lo, hi);
            B[m * 256 + n]     = fmaxf(lo + b1[n], 0.f);
            B[m * 256 + n + 1] = fmaxf(hi + b1[n + 1], 0.f);
        }
    // h = h1 @ W2 + b2   (no activation)
    gemm_tile2<4>(B, 256, 256, 256, W2, 256, Wsm, acc, tm, tn, tid);
#pragma unroll
    for (int i = 0; i < 8; i++)
#pragma unroll
        for (int j = 0; j < 4; j++) {
            int n = 2 * tn + 64 * j, m = tm + 8 * i;
            float lo, hi; unpack2(acc[i][j], lo, hi);
            A[m * A_STRIDE + n]     = lo + b2[n];
            A[m * A_STRIDE + n + 1] = hi + b2[n + 1];
        }
    __syncthreads();

    // gate logits into Wsm[64*8]
    for (int it = tid; it < 512; it += 256) {
        int m = it >> 3, e = it & 7;
        float s = bg[e];
        for (int k = 0; k < 256; k++) s = fmaf(A[m * A_STRIDE + k], Wg[k * 8 + e], s);
        Wsm[m * 8 + e] = s;
    }
    __syncthreads();

    if (tid < 64) {
        int gi = base + tid;
        if (gi < N) {
            float mx = Wsm[tid * 8]; int am = 0;
            for (int e = 1; e < 8; e++) { float v = Wsm[tid * 8 + e]; if (v > mx) { mx = v; am = e; } }
            float ssum = 0.f;
            for (int e = 0; e < 8; e++) ssum += expf(Wsm[tid * 8 + e] - mx);
            g_top1[gi] = am;
            g_gate[gi] = 1.f / ssum;       // softmax score at argmax
            atomicAdd(&g_counts[am], 1);
        }
    }

    // write h rows
    for (int i = tid; i < 64 * 64; i += 256) {
        int m = i >> 6, c4 = i & 63;
        int gi = base + m;
        if (gi < N)
            reinterpret_cast<float4*>(g_h + (size_t)gi * 256)[c4] =
                reinterpret_cast<const float4*>(A + m * A_STRIDE)[c4];
    }
}

// ---------------- routing helper kernels ----------------
__global__ void k_zero() {
    if (threadIdx.x < 8) g_counts[threadIdx.x] = 0;
}
__global__ void k_scan() {
    if (threadIdx.x == 0) {
        int off = 0;
        for (int e = 0; e < 8; e++) { g_cursor[e] = off; off += g_counts[e]; }
    }
}
__global__ void k_scatter(int N) {
    int i = blockIdx.x * 256 + threadIdx.x;
    if (i < N) {
        int e = g_top1[i];
        int pos = atomicAdd(&g_cursor[e], 1);
        g_perm[pos] = i;
    }
}

// ---------------- K4: routed expert MLP (4 layers, skip at layer 1) --------
__global__ void __launch_bounds__(256, 1)
k_expert(const float* __restrict__ We, const float* __restrict__ be, int N)
{
    extern __shared__ float sm[];
    float* A   = sm;
    float* B   = sm + SM_B;
    float* Wsm = sm + SM_W;
    __shared__ int   s_idx[64];
    __shared__ int   s_eo[64];
    __shared__ float s_gt[64];
    __shared__ int   s_mask;

    const int tid = threadIdx.x, tm = tid >> 5, tn = tid & 31;
    const int base = blockIdx.x * 64;

    if (tid < 64) {
        int gi = base + tid;
        int p = (gi < N) ? g_perm[gi] : -1;
        s_idx[tid] = p;
        s_eo[tid]  = (p >= 0) ? g_top1[p] : -1;
        s_gt[tid]  = (p >= 0) ? g_gate[p] : 0.f;
    }
    __syncthreads();
    if (tid == 0) {
        int mk = 0;
        for (int m = 0; m < 64; m++) if (s_eo[m] >= 0) mk |= 1 << s_eo[m];
        s_mask = mk;
    }
    __syncthreads();
    const int mask = s_mask;

    u64 acc[8][4];
    for (int e = 0; e < 8; e++) {
        if (!((mask >> e) & 1)) continue;

        // (re)load h rows into A (x for the skip connection)
        for (int i = tid; i < 64 * 64; i += 256) {
            int m = i >> 6, c4 = i & 63;
            int p = s_idx[m];
            float4 v = make_float4(0.f, 0.f, 0.f, 0.f);
            if (p >= 0) v = reinterpret_cast<const float4*>(g_h + (size_t)p * 256)[c4];
            reinterpret_cast<float4*>(A + m * A_STRIDE)[c4] = v;
        }

        const float* W  = We + (size_t)e * 4 * 256 * 256;
        const float* bb = be + (size_t)e * 4 * 256;

        // layer 0: B = relu(A @ W0 + b0)
        gemm_tile2<4>(A, A_STRIDE, 256, 256, W, 256, Wsm, acc, tm, tn, tid);
#pragma unroll
        for (int i = 0; i < 8; i++)
#pragma unroll
            for (int j = 0; j < 4; j++) {
                int n = 2 * tn + 64 * j, m = tm + 8 * i;
                float lo, hi; unpack2(acc[i][j], lo, hi);
                B[m * 256 + n]     = fmaxf(lo + bb[n], 0.f);
                B[m * 256 + n + 1] = fmaxf(hi + bb[n + 1], 0.f);
            }
        // layer 1 (skip): A = relu(B @ W1 + b1 + A)
        gemm_tile2<4>(B, 256, 256, 256, W + 65536, 256, Wsm, acc, tm, tn, tid);
#pragma unroll
        for (int i = 0; i < 8; i++)
#pragma unroll
            for (int j = 0; j < 4; j++) {
                int n = 2 * tn + 64 * j, m = tm + 8 * i;
                float lo, hi; unpack2(acc[i][j], lo, hi);
                float t0 = lo + bb[256 + n]     + A[m * A_STRIDE + n];
                float t1 = hi + bb[256 + n + 1] + A[m * A_STRIDE + n + 1];
                A[m * A_STRIDE + n]     = fmaxf(t0, 0.f);
                A[m * A_STRIDE + n + 1] = fmaxf(t1, 0.f);
            }
        // layer 2: B = relu(A @ W2 + b2)
        gemm_tile2<4>(A, A_STRIDE, 256, 256, W + 2 * 65536, 256, Wsm, acc, tm, tn, tid);
#pragma unroll
        for (int i = 0; i < 8; i++)
#pragma unroll
            for (int j = 0; j < 4; j++) {
                int n = 2 * tn + 64 * j, m = tm + 8 * i;
                float lo, hi; unpack2(acc[i][j], lo, hi);
                B[m * 256 + n]     = fmaxf(lo + bb[512 + n], 0.f);
                B[m * 256 + n + 1] = fmaxf(hi + bb[512 + n + 1], 0.f);
            }
        // layer 3: out = gate * (B @ W3 + b3), masked store
        gemm_tile2<4>(B, 256, 256, 256, W + 3 * 65536, 256, Wsm, acc, tm, tn, tid);
#pragma unroll
        for (int i = 0; i < 8; i++) {
            int m = tm + 8 * i;
            if (s_eo[m] == e) {
                int p = s_idx[m];
                float g = s_gt[m];
#pragma unroll
                for (int j = 0; j < 4; j++) {
                    int n = 2 * tn + 64 * j;
                    float lo, hi; unpack2(acc[i][j], lo, hi);
                    g_out[(size_t)p * 256 + n]     = g * (lo + bb[768 + n]);
                    g_out[(size_t)p * 256 + n + 1] = g * (hi + bb[768 + n + 1]);
                }
            }
        }
        __syncthreads();
    }
}

// ---------------- K5: sigma head + color head ----------------
__global__ void __launch_bounds__(256, 1)
k_heads(const float* __restrict__ dirs,
        const float* __restrict__ Ws1, const float* __restrict__ bs1,
        const float* __restrict__ Ws2, const float* __restrict__ bs2,
        const float* __restrict__ Wc1, const float* __restrict__ bc1,
        const float* __restrict__ Wc2, const float* __restrict__ bc2,
        float* __restrict__ out, int N)
{
    extern __shared__ float sm[];
    float* A   = sm;
    float* B   = sm + SM_B;          // c1: 64 x 128
    float* Bs  = B + 64 * 128;       // s1: 64 x 128
    float* Wsm = sm + SM_W;
    const int tid = threadIdx.x, tm = tid >> 5, tn = tid & 31;
    const int base = blockIdx.x * 64;

    // cin = [out(256), posenc(dirs)(27), pad(5 zeros)]
    for (int i = tid; i < 64 * 64; i += 256) {
        int m = i >> 6, c4 = i & 63;
        int gi = base + m; if (gi >= N) gi = N - 1;
        reinterpret_cast<float4*>(A + m * A_STRIDE)[c4] =
            reinterpret_cast<const float4*>(g_out + (size_t)gi * 256)[c4];
    }
    for (int i = tid; i < 64 * 32; i += 256) {
        int m = i >> 5, c = i & 31;
        int gi = base + m; if (gi >= N) gi = N - 1;
        float val = 0.f;
        if (c < 27) {
            if (c < 3) {
                val = dirs[gi * 3 + c];
            } else {
                int cc = c - 3, l = cc / 6, r = cc - 6 * l;
                float ax = dirs[gi * 3 + (r % 3)];
                float v = ax * (float)(1 << l);
                val = (r < 3) ? sinf(v) : cosf(v);
            }
        }
        A[m * A_STRIDE + 256 + c] = val;
    }

    u64 acc[8][2];
    // c1 = relu(cin @ Wc1 + bc1)   (Kd padded 288, real 283)
    gemm_tile2<2>(A, A_STRIDE, 288, 283, Wc1, 128, Wsm, acc, tm, tn, tid);
#pragma unroll
    for (int i = 0; i < 8; i++)
#pragma unroll
        for (int j = 0; j < 2; j++) {
            int n = 2 * tn + 64 * j, m = tm + 8 * i;
            float lo, hi; unpack2(acc[i][j], lo, hi);
            B[m * 128 + n]     = fmaxf(lo + bc1[n], 0.f);
            B[m * 128 + n + 1] = fmaxf(hi + bc1[n + 1], 0.f);
        }
    __syncthreads();

    // rgb = sigmoid(c1 @ Wc2 + bc2)
    for (int it = tid; it < 192; it += 256) {
        int m = it / 3, ch = it - 3 * m;
        float s = bc2[ch];
        for (int k = 0; k < 128; k++) s = fmaf(B[m * 128 + k], Wc2[k * 3 + ch], s);
        int gi = base + m;
        if (gi < N) out[gi * 4 + ch] = 1.f / (1.f + expf(-s));
    }

    // s1 = relu(out @ Ws1 + bs1)   (only first 256 cols of A)
    gemm_tile2<2>(A, A_STRIDE, 256, 256, Ws1, 128, Wsm, acc, tm, tn, tid);
#pragma unroll
    for (int i = 0; i < 8; i++)
#pragma unroll
        for (int j = 0; j < 2; j++) {
            int n = 2 * tn + 64 * j, m = tm + 8 * i;
            float lo, hi; unpack2(acc[i][j], lo, hi);
            Bs[m * 128 + n]     = fmaxf(lo + bs1[n], 0.f);
            Bs[m * 128 + n + 1] = fmaxf(hi + bs1[n + 1], 0.f);
        }
    __syncthreads();

    // sigma = softplus(s1 @ Ws2 + bs2)
    if (tid < 64) {
        int m = tid;
        float s = bs2[0];
        for (int k = 0; k < 128; k++) s = fmaf(Bs[m * 128 + k], Ws2[k], s);
        int gi = base + m;
        if (gi < N) {
            float sp = fmaxf(s, 0.f) + log1pf(expf(-fabsf(s)));
            out[gi * 4 + 3] = sp;
        }
    }
}

// ---------------- launch ----------------
extern "C" void kernel_launch(void* const* d_in, const int* in_sizes, int n_in,
                              void* d_out, int out_size)
{
    const float* xyz  = (const float*)d_in[0];
    const float* dirs = (const float*)d_in[1];
    const float* W1   = (const float*)d_in[2];
    const float* b1   = (const float*)d_in[3];
    const float* W2   = (const float*)d_in[4];
    const float* b2   = (const float*)d_in[5];
    const float* Wg   = (const float*)d_in[6];
    const float* bg   = (const float*)d_in[7];
    const float* We   = (const float*)d_in[8];
    const float* be   = (const float*)d_in[9];
    const float* Ws1  = (const float*)d_in[10];
    const float* bs1  = (const float*)d_in[11];
    const float* Ws2  = (const float*)d_in[12];
    const float* bs2  = (const float*)d_in[13];
    const float* Wc1  = (const float*)d_in[14];
    const float* bc1  = (const float*)d_in[15];
    const float* Wc2  = (const float*)d_in[16];
    const float* bc2  = (const float*)d_in[17];

    int N = in_sizes[0] / 3;
    if (N > NMAX) N = NMAX;

    const size_t smem = SMEM_FLOATS * sizeof(float);  // ~168 KB
    cudaFuncSetAttribute(k_trunk,  cudaFuncAttributeMaxDynamicSharedMemorySize, (int)smem);
    cudaFuncSetAttribute(k_expert, cudaFuncAttributeMaxDynamicSharedMemorySize, (int)smem);
    cudaFuncSetAttribute(k_heads,  cudaFuncAttributeMaxDynamicSharedMemorySize, (int)smem);

    int nb = (N + 63) / 64;

    k_zero<<<1, 32>>>();
    k_trunk<<<nb, 256, smem>>>(xyz, W1, b1, W2, b2, Wg, bg, N);
    k_scan<<<1, 32>>>();
    k_scatter<<<(N + 255) / 256, 256>>>(N);
    k_expert<<<nb, 256, smem>>>(We, be, N);
    k_heads<<<nb, 256, smem>>>(dirs, Ws1, bs1, Ws2, bs2, Wc1, bc1, Wc2, bc2,
                               (float*)d_out, N);
}